// round 1
// baseline (speedup 1.0000x reference)
#include <cuda_runtime.h>

// Problem constants
#define BZ 2
#define SQ 2048
#define DH 1024
#define NH 16
#define HDIM 64

// Scratch (no cudaMalloc allowed): qkv [2,2048,3072], attn-out [2,2048,1024]
__device__ float g_qkv[(size_t)BZ * SQ * 3 * DH];
__device__ float g_att[(size_t)BZ * SQ * DH];

// ---------------------------------------------------------------------------
// GEMM (NT): C[M,N] = A[M,K] * B[N,K]^T, all row-major, fp32.
// Tiles: BM=BN=64, BK=32. 256 threads, each computes a 4x4 micro-tile.
// ---------------------------------------------------------------------------
__global__ void gemm_nt64(const float* __restrict__ A,
                          const float* __restrict__ B,
                          float* __restrict__ C,
                          int M, int N, int K) {
    __shared__ float As[32][65];
    __shared__ float Bs[32][65];

    const int bm = blockIdx.y * 64;
    const int bn = blockIdx.x * 64;
    const int tid = threadIdx.x;
    const int tx = tid & 15;        // 0..15 -> 4 cols each
    const int ty = tid >> 4;        // 0..15 -> 4 rows each
    const int lc = tid & 31;        // k-col for loads
    const int lr0 = tid >> 5;       // row start for loads (0..7)

    float acc[4][4] = {};

    for (int k0 = 0; k0 < K; k0 += 32) {
        #pragma unroll
        for (int r = lr0; r < 64; r += 8) {
            As[lc][r] = A[(size_t)(bm + r) * K + k0 + lc];
            Bs[lc][r] = B[(size_t)(bn + r) * K + k0 + lc];
        }
        __syncthreads();

        #pragma unroll
        for (int k = 0; k < 32; k++) {
            float a[4], bb[4];
            #pragma unroll
            for (int i = 0; i < 4; i++) a[i] = As[k][ty * 4 + i];
            #pragma unroll
            for (int j = 0; j < 4; j++) bb[j] = Bs[k][tx * 4 + j];
            #pragma unroll
            for (int i = 0; i < 4; i++)
                #pragma unroll
                for (int j = 0; j < 4; j++)
                    acc[i][j] = fmaf(a[i], bb[j], acc[i][j]);
        }
        __syncthreads();
    }

    #pragma unroll
    for (int i = 0; i < 4; i++)
        #pragma unroll
        for (int j = 0; j < 4; j++)
            C[(size_t)(bm + ty * 4 + i) * N + bn + tx * 4 + j] = acc[i][j];
}

// ---------------------------------------------------------------------------
// Flash-attention (fp32): one block = 64 query rows of one (b,h).
// KV processed in tiles of 32 rows with online softmax.
// qkv layout: [b, s, 3*DH] with q at col h*64, k at 1024+h*64, v at 2048+h*64.
// Output written as [b, s, h*64 + d] (i.e. [b,s,1024], ready for out-proj GEMM).
// ---------------------------------------------------------------------------
__global__ void attn64(const float* __restrict__ qkv, float* __restrict__ out) {
    const int bh = blockIdx.y;          // 0..31
    const int b = bh >> 4;
    const int h = bh & 15;
    const int q0 = blockIdx.x * 64;

    __shared__ float Qs[64][65];
    __shared__ float Ks[32][65];
    __shared__ float Vs[32][65];
    __shared__ float Ps[64][33];
    __shared__ float m_s[64], l_s[64], sc_s[64];

    const int tid = threadIdx.x;
    const int tx = tid & 15;
    const int ty = tid >> 4;
    const float scale = 0.125f;   // HDIM^-0.5 (exact)

    // Load Q tile (pre-scaled)
    {
        const int cc = tid & 63;
        const int rr = tid >> 6;
        #pragma unroll
        for (int r = rr; r < 64; r += 4)
            Qs[r][cc] = qkv[(size_t)(b * SQ + q0 + r) * (3 * DH) + h * HDIM + cc] * scale;
    }
    if (tid < 64) { m_s[tid] = -1e30f; l_s[tid] = 0.0f; }

    float acc[4][4] = {};
    __syncthreads();

    for (int kt = 0; kt < SQ / 32; kt++) {
        const int kv0 = kt * 32;
        // Load K,V tiles (32 rows x 64 cols each)
        {
            const int cc = tid & 63;
            const int rr = tid >> 6;
            #pragma unroll
            for (int r = rr; r < 32; r += 4) {
                const size_t base = (size_t)(b * SQ + kv0 + r) * (3 * DH) + h * HDIM + cc;
                Ks[r][cc] = qkv[base + DH];
                Vs[r][cc] = qkv[base + 2 * DH];
            }
        }
        __syncthreads();

        // S = Q * K^T for this tile: thread owns 4 q-rows x 2 kv-cols
        float s[4][2] = {};
        #pragma unroll
        for (int k = 0; k < 64; k++) {
            float a[4], b0, b1;
            #pragma unroll
            for (int i = 0; i < 4; i++) a[i] = Qs[ty * 4 + i][k];
            b0 = Ks[tx * 2][k];
            b1 = Ks[tx * 2 + 1][k];
            #pragma unroll
            for (int i = 0; i < 4; i++) {
                s[i][0] = fmaf(a[i], b0, s[i][0]);
                s[i][1] = fmaf(a[i], b1, s[i][1]);
            }
        }
        #pragma unroll
        for (int i = 0; i < 4; i++) {
            Ps[ty * 4 + i][tx * 2]     = s[i][0];
            Ps[ty * 4 + i][tx * 2 + 1] = s[i][1];
        }
        __syncthreads();

        // Online softmax row pass: one thread per query row
        if (tid < 64) {
            const float mold = m_s[tid];
            float rm = mold;
            #pragma unroll
            for (int c = 0; c < 32; c++) rm = fmaxf(rm, Ps[tid][c]);
            const float sc = expf(mold - rm);   // first tile: exp(-1e30 - finite) = 0
            float rs = 0.0f;
            #pragma unroll
            for (int c = 0; c < 32; c++) {
                const float p = expf(Ps[tid][c] - rm);
                Ps[tid][c] = p;
                rs += p;
            }
            m_s[tid] = rm;
            sc_s[tid] = sc;
            l_s[tid] = l_s[tid] * sc + rs;
        }
        __syncthreads();

        // Rescale accumulators, then O += P * V (thread: 4 rows x 4 cols)
        #pragma unroll
        for (int i = 0; i < 4; i++) {
            const float sc = sc_s[ty * 4 + i];
            #pragma unroll
            for (int j = 0; j < 4; j++) acc[i][j] *= sc;
        }
        #pragma unroll
        for (int k = 0; k < 32; k++) {
            float p[4], v[4];
            #pragma unroll
            for (int i = 0; i < 4; i++) p[i] = Ps[ty * 4 + i][k];
            #pragma unroll
            for (int j = 0; j < 4; j++) v[j] = Vs[k][tx * 4 + j];
            #pragma unroll
            for (int i = 0; i < 4; i++)
                #pragma unroll
                for (int j = 0; j < 4; j++)
                    acc[i][j] = fmaf(p[i], v[j], acc[i][j]);
        }
        __syncthreads();
    }

    // Normalize and store
    #pragma unroll
    for (int i = 0; i < 4; i++) {
        const float inv = 1.0f / l_s[ty * 4 + i];
        #pragma unroll
        for (int j = 0; j < 4; j++)
            out[(size_t)(b * SQ + q0 + ty * 4 + i) * DH + h * HDIM + tx * 4 + j] =
                acc[i][j] * inv;
    }
}

extern "C" void kernel_launch(void* const* d_in, const int* in_sizes, int n_in,
                              void* d_out, int out_size) {
    const float* x     = (const float*)d_in[0];
    const float* w_qkv = (const float*)d_in[1];
    const float* w_out = (const float*)d_in[2];
    float* out = (float*)d_out;

    float* qkv = nullptr;
    float* att = nullptr;
    cudaGetSymbolAddress((void**)&qkv, g_qkv);
    cudaGetSymbolAddress((void**)&att, g_att);

    const int M = BZ * SQ;   // 4096

    // 1) QKV projection: [4096,1024] x [3072,1024]^T -> [4096,3072]
    gemm_nt64<<<dim3(3 * DH / 64, M / 64), 256>>>(x, w_qkv, qkv, M, 3 * DH, DH);

    // 2) Attention: grid (q-tiles=32, b*h=32)
    attn64<<<dim3(SQ / 64, BZ * NH), 256>>>(qkv, att);

    // 3) Output projection: [4096,1024] x [1024,1024]^T -> [4096,1024]
    gemm_nt64<<<dim3(DH / 64, M / 64), 256>>>(att, w_out, out, M, DH, DH);
}

// round 3
// speedup vs baseline: 1.6267x; 1.6267x over previous
#include <cuda_runtime.h>
#include <cuda_bf16.h>
#include <cstdint>

// Problem constants
#define BZ 2
#define SQ 2048
#define DH 1024
#define NH 16
#define HDIM 64

// ---------------------------------------------------------------------------
// Scratch (no cudaMalloc allowed)
// ---------------------------------------------------------------------------
__device__ __align__(16) float g_qkv[(size_t)BZ * SQ * 3 * DH];   // [2,2048,3072]
__device__ __align__(16) float g_att[(size_t)BZ * SQ * DH];       // [2,2048,1024]
__device__ __align__(16) __nv_bfloat16 g_xh[(size_t)BZ * SQ * DH];
__device__ __align__(16) __nv_bfloat16 g_xl[(size_t)BZ * SQ * DH];
__device__ __align__(16) __nv_bfloat16 g_wqh[(size_t)3 * DH * DH];
__device__ __align__(16) __nv_bfloat16 g_wql[(size_t)3 * DH * DH];
__device__ __align__(16) __nv_bfloat16 g_woh[(size_t)DH * DH];
__device__ __align__(16) __nv_bfloat16 g_wol[(size_t)DH * DH];
__device__ __align__(16) __nv_bfloat16 g_ah[(size_t)BZ * SQ * DH];
__device__ __align__(16) __nv_bfloat16 g_al[(size_t)BZ * SQ * DH];

// ---------------------------------------------------------------------------
// Portable PTX helpers (no arch-"a" features: ldmatrix / mma.sync / cp.async)
// ---------------------------------------------------------------------------
__device__ __forceinline__ uint32_t smem_to_u32(const void* p) {
    uint32_t a;
    asm("{ .reg .u64 t; cvta.to.shared.u64 t, %1; cvt.u32.u64 %0, t; }"
        : "=r"(a) : "l"(p));
    return a;
}

__device__ __forceinline__ void cp16(uint32_t saddr, const void* gaddr) {
    asm volatile("cp.async.cg.shared.global [%0], [%1], 16;"
                 :: "r"(saddr), "l"(gaddr));
}
#define CP_COMMIT() asm volatile("cp.async.commit_group;" ::: "memory")
#define CP_WAIT(n)  asm volatile("cp.async.wait_group %0;" :: "n"(n) : "memory")

__device__ __forceinline__ void ldmx4(uint32_t* r, uint32_t addr) {
    asm volatile("ldmatrix.sync.aligned.m8n8.x4.shared.b16 {%0,%1,%2,%3}, [%4];"
                 : "=r"(r[0]), "=r"(r[1]), "=r"(r[2]), "=r"(r[3]) : "r"(addr));
}

__device__ __forceinline__ void mma_bf16(float* d, const uint32_t* a,
                                         uint32_t b0, uint32_t b1) {
    asm volatile(
        "mma.sync.aligned.m16n8k16.row.col.f32.bf16.bf16.f32 "
        "{%0,%1,%2,%3}, {%4,%5,%6,%7}, {%8,%9}, {%0,%1,%2,%3};"
        : "+f"(d[0]), "+f"(d[1]), "+f"(d[2]), "+f"(d[3])
        : "r"(a[0]), "r"(a[1]), "r"(a[2]), "r"(a[3]), "r"(b0), "r"(b1));
}

// ---------------------------------------------------------------------------
// fp32 -> bf16 hi/lo split (4 elems/thread)
// ---------------------------------------------------------------------------
__global__ void split_hl(const float4* __restrict__ x,
                         uint2* __restrict__ hi, uint2* __restrict__ lo, int n4) {
    int i = blockIdx.x * blockDim.x + threadIdx.x;
    if (i >= n4) return;
    float4 v = x[i];
    union { __nv_bfloat16 b[4]; uint2 u; } H, L;
    float f[4] = {v.x, v.y, v.z, v.w};
    #pragma unroll
    for (int j = 0; j < 4; j++) {
        __nv_bfloat16 h = __float2bfloat16(f[j]);
        H.b[j] = h;
        L.b[j] = __float2bfloat16(f[j] - __bfloat162float(h));
    }
    hi[i] = H.u;
    lo[i] = L.u;
}

// ---------------------------------------------------------------------------
// Split-bf16 HMMA GEMM (NT): C[M,N] = (Ah+Al)[M,K] * (Bh+Bl)[N,K]^T  (fp32 out)
// CTA tile 128x128, K-chunk 64, 3-stage cp.async pipeline, 256 threads.
// Stage layout (64KB): Ah(16K) Al(16K) Bh(16K) Bl(16K); tiles are 128 rows x
// 128B (64 bf16), SW128-swizzled: phys = off ^ ((off>>3)&0x70).
// Warps 2(m) x 4(n): warp tile 64x32. mma.sync m16n8k16 bf16->f32.
// ---------------------------------------------------------------------------
#define NSTAGE 3
#define STAGE_BYTES 65536
#define GSM_TOTAL (NSTAGE * STAGE_BYTES)

__global__ void __launch_bounds__(256, 1) gemm_mma(
    const __nv_bfloat16* __restrict__ Ah, const __nv_bfloat16* __restrict__ Al,
    const __nv_bfloat16* __restrict__ Bh, const __nv_bfloat16* __restrict__ Bl,
    float* __restrict__ C, int M, int N, int K) {
    extern __shared__ char smem[];
    const uint32_t sb = smem_to_u32(smem);
    const int tid = threadIdx.x;
    const int lane = tid & 31;
    const int wid = tid >> 5;
    const int bm = blockIdx.y * 128;
    const int bn = blockIdx.x * 128;
    const int wm = (wid >> 2) * 64;   // warp m-offset in CTA tile
    const int wn = (wid & 3) * 32;    // warp n-offset

    // cp.async per-thread mapping: 4 chunks per sub-tile, 4 sub-tiles
    // (each sub-tile: 128 rows x 128B = 1024 x 16B chunks / 256 threads)
    auto issue_stage = [&](int ch) {
        const int k0 = ch << 6;
        const uint32_t buf = sb + (uint32_t)(ch % NSTAGE) * STAGE_BYTES;
        #pragma unroll
        for (int i = 0; i < 4; i++) {
            int lin = tid + (i << 8);
            int row = lin >> 3;
            int c8 = lin & 7;
            uint32_t off = (uint32_t)(row << 7) + (uint32_t)(c8 << 4);
            uint32_t sw = off ^ ((off >> 3) & 0x70);
            size_t ga = (size_t)(bm + row) * K + k0 + (c8 << 3);
            size_t gb = (size_t)(bn + row) * K + k0 + (c8 << 3);
            cp16(buf + sw,         Ah + ga);
            cp16(buf + 16384 + sw, Al + ga);
            cp16(buf + 32768 + sw, Bh + gb);
            cp16(buf + 49152 + sw, Bl + gb);
        }
    };

    // ldmatrix address components (SW128-aware)
    const uint32_t xorv   = (uint32_t)(lane & 7) << 4;
    const uint32_t aRowOff = (uint32_t)((wm + (lane & 15)) << 7);
    const uint32_t kaoff  = (uint32_t)((lane >> 4) << 4);          // A k-half
    const uint32_t bRowOff =
        (uint32_t)((wn + (lane & 7) + (((lane >> 4) & 1) << 3)) << 7);
    const uint32_t kboff  = (uint32_t)(((lane >> 3) & 1) << 4);    // B k-half

    float acc[4][4][4] = {};

    const int KCHUNKS = K >> 6;
    // Prologue: prefetch 2 stages
    issue_stage(0); CP_COMMIT();
    issue_stage(1); CP_COMMIT();

    for (int ch = 0; ch < KCHUNKS; ch++) {
        CP_WAIT(1);          // stage ch complete
        __syncthreads();     // all warps past compute(ch-1); buffer reuse safe
        if (ch + 2 < KCHUNKS) issue_stage(ch + 2);
        CP_COMMIT();         // always commit (keeps group accounting exact)

        const uint32_t buf = sb + (uint32_t)(ch % NSTAGE) * STAGE_BYTES;
        const uint32_t aHi = buf + aRowOff;
        const uint32_t aLo = aHi + 16384;
        const uint32_t bHi = buf + 32768 + bRowOff;
        const uint32_t bLo = bHi + 16384;

        #pragma unroll
        for (int s = 0; s < 4; s++) {            // 4 x k16 within the chunk
            const uint32_t ca = ((uint32_t)(s << 5) + kaoff) ^ xorv;
            const uint32_t cb = ((uint32_t)(s << 5) + kboff) ^ xorv;
            uint32_t ah4[4][4], al4[4][4], bh4[2][4], bl4[2][4];
            #pragma unroll
            for (int mt = 0; mt < 4; mt++) {     // 4 x m16 tiles
                ldmx4(ah4[mt], aHi + (mt << 11) + ca);
                ldmx4(al4[mt], aLo + (mt << 11) + ca);
            }
            #pragma unroll
            for (int nt2 = 0; nt2 < 2; nt2++) {  // 2 x n16 tiles
                ldmx4(bh4[nt2], bHi + (nt2 << 11) + cb);
                ldmx4(bl4[nt2], bLo + (nt2 << 11) + cb);
            }
            #pragma unroll
            for (int mt = 0; mt < 4; mt++)
                #pragma unroll
                for (int nt = 0; nt < 4; nt++) {
                    const uint32_t b0h = bh4[nt >> 1][(nt & 1) * 2];
                    const uint32_t b1h = bh4[nt >> 1][(nt & 1) * 2 + 1];
                    const uint32_t b0l = bl4[nt >> 1][(nt & 1) * 2];
                    const uint32_t b1l = bl4[nt >> 1][(nt & 1) * 2 + 1];
                    mma_bf16(acc[mt][nt], ah4[mt], b0h, b1h);  // hi*hi
                    mma_bf16(acc[mt][nt], ah4[mt], b0l, b1l);  // hi*lo
                    mma_bf16(acc[mt][nt], al4[mt], b0h, b1h);  // lo*hi
                }
        }
    }
    CP_WAIT(0);

    // Epilogue: d-fragment m16n8 layout: d0,d1 -> (row=lane>>2, col=(lane&3)*2),
    // d2,d3 -> row+8
    #pragma unroll
    for (int mt = 0; mt < 4; mt++) {
        const int r0 = bm + wm + mt * 16 + (lane >> 2);
        #pragma unroll
        for (int nt = 0; nt < 4; nt++) {
            const int c = bn + wn + nt * 8 + (lane & 3) * 2;
            float2 v0 = make_float2(acc[mt][nt][0], acc[mt][nt][1]);
            float2 v1 = make_float2(acc[mt][nt][2], acc[mt][nt][3]);
            *(float2*)&C[(size_t)r0 * N + c]       = v0;
            *(float2*)&C[(size_t)(r0 + 8) * N + c] = v1;
        }
    }
}

// ---------------------------------------------------------------------------
// Flash-attention (fp32) — unchanged (passing, ~1140us; R4 target)
// ---------------------------------------------------------------------------
__global__ void attn64(const float* __restrict__ qkv, float* __restrict__ out) {
    const int bh = blockIdx.y;
    const int b = bh >> 4;
    const int h = bh & 15;
    const int q0 = blockIdx.x * 64;

    __shared__ float Qs[64][65];
    __shared__ float Ks[32][65];
    __shared__ float Vs[32][65];
    __shared__ float Ps[64][33];
    __shared__ float m_s[64], l_s[64], sc_s[64];

    const int tid = threadIdx.x;
    const int tx = tid & 15;
    const int ty = tid >> 4;
    const float scale = 0.125f;

    {
        const int cc = tid & 63;
        const int rr = tid >> 6;
        #pragma unroll
        for (int r = rr; r < 64; r += 4)
            Qs[r][cc] = qkv[(size_t)(b * SQ + q0 + r) * (3 * DH) + h * HDIM + cc] * scale;
    }
    if (tid < 64) { m_s[tid] = -1e30f; l_s[tid] = 0.0f; }

    float acc[4][4] = {};
    __syncthreads();

    for (int kt = 0; kt < SQ / 32; kt++) {
        const int kv0 = kt * 32;
        {
            const int cc = tid & 63;
            const int rr = tid >> 6;
            #pragma unroll
            for (int r = rr; r < 32; r += 4) {
                const size_t base = (size_t)(b * SQ + kv0 + r) * (3 * DH) + h * HDIM + cc;
                Ks[r][cc] = qkv[base + DH];
                Vs[r][cc] = qkv[base + 2 * DH];
            }
        }
        __syncthreads();

        float s[4][2] = {};
        #pragma unroll
        for (int k = 0; k < 64; k++) {
            float a[4], b0, b1;
            #pragma unroll
            for (int i = 0; i < 4; i++) a[i] = Qs[ty * 4 + i][k];
            b0 = Ks[tx * 2][k];
            b1 = Ks[tx * 2 + 1][k];
            #pragma unroll
            for (int i = 0; i < 4; i++) {
                s[i][0] = fmaf(a[i], b0, s[i][0]);
                s[i][1] = fmaf(a[i], b1, s[i][1]);
            }
        }
        #pragma unroll
        for (int i = 0; i < 4; i++) {
            Ps[ty * 4 + i][tx * 2]     = s[i][0];
            Ps[ty * 4 + i][tx * 2 + 1] = s[i][1];
        }
        __syncthreads();

        if (tid < 64) {
            const float mold = m_s[tid];
            float rm = mold;
            #pragma unroll
            for (int c = 0; c < 32; c++) rm = fmaxf(rm, Ps[tid][c]);
            const float sc = expf(mold - rm);
            float rs = 0.0f;
            #pragma unroll
            for (int c = 0; c < 32; c++) {
                const float p = expf(Ps[tid][c] - rm);
                Ps[tid][c] = p;
                rs += p;
            }
            m_s[tid] = rm;
            sc_s[tid] = sc;
            l_s[tid] = l_s[tid] * sc + rs;
        }
        __syncthreads();

        #pragma unroll
        for (int i = 0; i < 4; i++) {
            const float sc = sc_s[ty * 4 + i];
            #pragma unroll
            for (int j = 0; j < 4; j++) acc[i][j] *= sc;
        }
        #pragma unroll
        for (int k = 0; k < 32; k++) {
            float p[4], v[4];
            #pragma unroll
            for (int i = 0; i < 4; i++) p[i] = Ps[ty * 4 + i][k];
            #pragma unroll
            for (int j = 0; j < 4; j++) v[j] = Vs[k][tx * 4 + j];
            #pragma unroll
            for (int i = 0; i < 4; i++)
                #pragma unroll
                for (int j = 0; j < 4; j++)
                    acc[i][j] = fmaf(p[i], v[j], acc[i][j]);
        }
        __syncthreads();
    }

    #pragma unroll
    for (int i = 0; i < 4; i++) {
        const float inv = 1.0f / l_s[ty * 4 + i];
        #pragma unroll
        for (int j = 0; j < 4; j++)
            out[(size_t)(b * SQ + q0 + ty * 4 + i) * DH + h * HDIM + tx * 4 + j] =
                acc[i][j] * inv;
    }
}

// ---------------------------------------------------------------------------
extern "C" void kernel_launch(void* const* d_in, const int* in_sizes, int n_in,
                              void* d_out, int out_size) {
    const float* x     = (const float*)d_in[0];
    const float* w_qkv = (const float*)d_in[1];
    const float* w_out = (const float*)d_in[2];
    float* out = (float*)d_out;

    float *qkv, *att;
    __nv_bfloat16 *xh, *xl, *wqh, *wql, *woh, *wol, *ah, *al;
    cudaGetSymbolAddress((void**)&qkv, g_qkv);
    cudaGetSymbolAddress((void**)&att, g_att);
    cudaGetSymbolAddress((void**)&xh, g_xh);
    cudaGetSymbolAddress((void**)&xl, g_xl);
    cudaGetSymbolAddress((void**)&wqh, g_wqh);
    cudaGetSymbolAddress((void**)&wql, g_wql);
    cudaGetSymbolAddress((void**)&woh, g_woh);
    cudaGetSymbolAddress((void**)&wol, g_wol);
    cudaGetSymbolAddress((void**)&ah, g_ah);
    cudaGetSymbolAddress((void**)&al, g_al);

    cudaFuncSetAttribute(gemm_mma, cudaFuncAttributeMaxDynamicSharedMemorySize,
                         GSM_TOTAL);

    const int M = BZ * SQ;                 // 4096
    const int nX  = M * DH / 4;
    const int nWq = 3 * DH * DH / 4;
    const int nWo = DH * DH / 4;

    // Split inputs/weights into bf16 hi/lo
    split_hl<<<(nX + 255) / 256, 256>>>((const float4*)x, (uint2*)xh, (uint2*)xl, nX);
    split_hl<<<(nWq + 255) / 256, 256>>>((const float4*)w_qkv, (uint2*)wqh, (uint2*)wql, nWq);
    split_hl<<<(nWo + 255) / 256, 256>>>((const float4*)w_out, (uint2*)woh, (uint2*)wol, nWo);

    // 1) QKV projection: [4096,1024] x [3072,1024]^T -> [4096,3072] (fp32)
    gemm_mma<<<dim3(3 * DH / 128, M / 128), 256, GSM_TOTAL>>>(xh, xl, wqh, wql,
                                                              qkv, M, 3 * DH, DH);

    // 2) Attention
    attn64<<<dim3(SQ / 64, BZ * NH), 256>>>(qkv, att);

    // 3) Split attention output, then output projection -> d_out (fp32)
    const int nA = M * DH / 4;
    split_hl<<<(nA + 255) / 256, 256>>>((const float4*)att, (uint2*)ah, (uint2*)al, nA);
    gemm_mma<<<dim3(DH / 128, M / 128), 256, GSM_TOTAL>>>(ah, al, woh, wol, out,
                                                          M, DH, DH);
}

// round 4
// speedup vs baseline: 4.0007x; 2.4593x over previous
#include <cuda_runtime.h>
#include <cuda_bf16.h>
#include <cstdint>

// Problem constants
#define BZ 2
#define SQ 2048
#define DH 1024
#define NH 16
#define HDIM 64

// 0.125 * log2(e): folded into Q so softmax runs in the exp2 domain
#define SCALE_LOG2 0.18033688011112042f

// ---------------------------------------------------------------------------
// Scratch (no cudaMalloc allowed)
// ---------------------------------------------------------------------------
__device__ __align__(16) float g_qkv[(size_t)BZ * SQ * 3 * DH];   // [2,2048,3072]
__device__ __align__(16) __nv_bfloat16 g_xh[(size_t)BZ * SQ * DH];
__device__ __align__(16) __nv_bfloat16 g_xl[(size_t)BZ * SQ * DH];
__device__ __align__(16) __nv_bfloat16 g_wqh[(size_t)3 * DH * DH];
__device__ __align__(16) __nv_bfloat16 g_wql[(size_t)3 * DH * DH];
__device__ __align__(16) __nv_bfloat16 g_woh[(size_t)DH * DH];
__device__ __align__(16) __nv_bfloat16 g_wol[(size_t)DH * DH];
// head-major attention operands
__device__ __align__(16) __nv_bfloat16 g_Qh[(size_t)BZ * NH * SQ * HDIM];
__device__ __align__(16) __nv_bfloat16 g_Ql[(size_t)BZ * NH * SQ * HDIM];
__device__ __align__(16) __nv_bfloat16 g_Kh[(size_t)BZ * NH * SQ * HDIM];
__device__ __align__(16) __nv_bfloat16 g_Kl[(size_t)BZ * NH * SQ * HDIM];
__device__ __align__(16) __nv_bfloat16 g_Vth[(size_t)BZ * NH * HDIM * SQ];
__device__ __align__(16) __nv_bfloat16 g_Vtl[(size_t)BZ * NH * HDIM * SQ];
// attention output (split, [b,s,1024])
__device__ __align__(16) __nv_bfloat16 g_ah[(size_t)BZ * SQ * DH];
__device__ __align__(16) __nv_bfloat16 g_al[(size_t)BZ * SQ * DH];

// ---------------------------------------------------------------------------
// PTX helpers (portable sm_80+ subset; no arch-"a" features)
// ---------------------------------------------------------------------------
__device__ __forceinline__ uint32_t smem_to_u32(const void* p) {
    uint32_t a;
    asm("{ .reg .u64 t; cvta.to.shared.u64 t, %1; cvt.u32.u64 %0, t; }"
        : "=r"(a) : "l"(p));
    return a;
}

__device__ __forceinline__ void cp16(uint32_t saddr, const void* gaddr) {
    asm volatile("cp.async.cg.shared.global [%0], [%1], 16;"
                 :: "r"(saddr), "l"(gaddr));
}
#define CP_COMMIT() asm volatile("cp.async.commit_group;" ::: "memory")
#define CP_WAIT(n)  asm volatile("cp.async.wait_group %0;" :: "n"(n) : "memory")

__device__ __forceinline__ void ldmx4(uint32_t* r, uint32_t addr) {
    asm volatile("ldmatrix.sync.aligned.m8n8.x4.shared.b16 {%0,%1,%2,%3}, [%4];"
                 : "=r"(r[0]), "=r"(r[1]), "=r"(r[2]), "=r"(r[3]) : "r"(addr));
}

__device__ __forceinline__ void mma_bf16(float* d, const uint32_t* a,
                                         uint32_t b0, uint32_t b1) {
    asm volatile(
        "mma.sync.aligned.m16n8k16.row.col.f32.bf16.bf16.f32 "
        "{%0,%1,%2,%3}, {%4,%5,%6,%7}, {%8,%9}, {%0,%1,%2,%3};"
        : "+f"(d[0]), "+f"(d[1]), "+f"(d[2]), "+f"(d[3])
        : "r"(a[0]), "r"(a[1]), "r"(a[2]), "r"(a[3]), "r"(b0), "r"(b1));
}

__device__ __forceinline__ float ex2f(float x) {
    float r;
    asm("ex2.approx.f32 %0, %1;" : "=f"(r) : "f"(x));
    return r;
}
// {lo16 = hi-bf16 of a, hi16 = hi-bf16 of b}  (truncation split, a,b >= 0 ok)
__device__ __forceinline__ uint32_t prmt_hi2(uint32_t a, uint32_t b) {
    uint32_t d;
    asm("prmt.b32 %0, %1, %2, 0x7632;" : "=r"(d) : "r"(a), "r"(b));
    return d;
}
// pack {lo16 = bf16(lo_elem), hi16 = bf16(hi_elem)} with round-to-nearest
__device__ __forceinline__ uint32_t packbf2(float hi_elem, float lo_elem) {
    uint32_t d;
    asm("cvt.rn.bf16x2.f32 %0, %1, %2;" : "=r"(d) : "f"(hi_elem), "f"(lo_elem));
    return d;
}

__device__ __forceinline__ void split4(float4 v, uint2& hi, uint2& lo) {
    union { __nv_bfloat16 b[4]; uint2 u; } H, L;
    float f[4] = {v.x, v.y, v.z, v.w};
    #pragma unroll
    for (int j = 0; j < 4; j++) {
        __nv_bfloat16 h = __float2bfloat16(f[j]);
        H.b[j] = h;
        L.b[j] = __float2bfloat16(f[j] - __bfloat162float(h));
    }
    hi = H.u; lo = L.u;
}

// ---------------------------------------------------------------------------
// fp32 -> bf16 hi/lo split (4 elems/thread)
// ---------------------------------------------------------------------------
__global__ void split_hl(const float4* __restrict__ x,
                         uint2* __restrict__ hi, uint2* __restrict__ lo, int n4) {
    int i = blockIdx.x * blockDim.x + threadIdx.x;
    if (i >= n4) return;
    uint2 H, L;
    split4(x[i], H, L);
    hi[i] = H; lo[i] = L;
}

// ---------------------------------------------------------------------------
// prep_qkv: qkv fp32 [b,s,3072] -> head-major bf16 hi/lo:
//   Q*(0.125*log2e) -> [bh, s, 64];  K -> [bh, s, 64];  V^T -> [bh, 64, s]
// grid (32 s-tiles of 64, 32 bh), 256 threads
// ---------------------------------------------------------------------------
__global__ void prep_qkv(const float* __restrict__ qkv,
                         uint2* __restrict__ Qh, uint2* __restrict__ Ql,
                         uint2* __restrict__ Kh, uint2* __restrict__ Kl,
                         uint2* __restrict__ Vth, uint2* __restrict__ Vtl) {
    __shared__ float Vs[64][65];
    const int bh = blockIdx.y;
    const int b = bh >> 4, h = bh & 15;
    const int s0 = blockIdx.x * 64;
    const int tid = threadIdx.x;

    #pragma unroll
    for (int it = 0; it < 4; it++) {
        int lin = it * 256 + tid;
        int row = lin >> 4;     // 0..63
        int c4 = lin & 15;      // float4 index within 64-col row
        const float* base = qkv + ((size_t)(b * SQ + s0 + row)) * (3 * DH)
                                + h * HDIM + c4 * 4;
        float4 q = *(const float4*)base;
        float4 k = *(const float4*)(base + DH);
        float4 v = *(const float4*)(base + 2 * DH);
        q.x *= SCALE_LOG2; q.y *= SCALE_LOG2; q.z *= SCALE_LOG2; q.w *= SCALE_LOG2;
        uint2 H, L;
        size_t qi = (((size_t)bh * SQ + s0 + row) * HDIM + c4 * 4) >> 2;
        split4(q, H, L); Qh[qi] = H; Ql[qi] = L;
        split4(k, H, L); Kh[qi] = H; Kl[qi] = L;
        Vs[row][c4 * 4 + 0] = v.x;
        Vs[row][c4 * 4 + 1] = v.y;
        Vs[row][c4 * 4 + 2] = v.z;
        Vs[row][c4 * 4 + 3] = v.w;
    }
    __syncthreads();
    #pragma unroll
    for (int it = 0; it < 4; it++) {
        int lin = it * 256 + tid;
        int hd = lin >> 4;      // 0..63
        int c = lin & 15;       // group of 4 s positions
        float4 v;
        v.x = Vs[c * 4 + 0][hd];
        v.y = Vs[c * 4 + 1][hd];
        v.z = Vs[c * 4 + 2][hd];
        v.w = Vs[c * 4 + 3][hd];
        uint2 H, L;
        split4(v, H, L);
        size_t vi = (((size_t)bh * HDIM + hd) * SQ + s0 + c * 4) >> 2;
        Vth[vi] = H; Vtl[vi] = L;
    }
}

// ---------------------------------------------------------------------------
// Split-bf16 HMMA GEMM (NT) — unchanged from R3 (passing, 61% tensor)
// ---------------------------------------------------------------------------
#define NSTAGE 3
#define STAGE_BYTES 65536
#define GSM_TOTAL (NSTAGE * STAGE_BYTES)

__global__ void __launch_bounds__(256, 1) gemm_mma(
    const __nv_bfloat16* __restrict__ Ah, const __nv_bfloat16* __restrict__ Al,
    const __nv_bfloat16* __restrict__ Bh, const __nv_bfloat16* __restrict__ Bl,
    float* __restrict__ C, int M, int N, int K) {
    extern __shared__ char smem[];
    const uint32_t sb = smem_to_u32(smem);
    const int tid = threadIdx.x;
    const int lane = tid & 31;
    const int wid = tid >> 5;
    const int bm = blockIdx.y * 128;
    const int bn = blockIdx.x * 128;
    const int wm = (wid >> 2) * 64;
    const int wn = (wid & 3) * 32;

    auto issue_stage = [&](int ch) {
        const int k0 = ch << 6;
        const uint32_t buf = sb + (uint32_t)(ch % NSTAGE) * STAGE_BYTES;
        #pragma unroll
        for (int i = 0; i < 4; i++) {
            int lin = tid + (i << 8);
            int row = lin >> 3;
            int c8 = lin & 7;
            uint32_t off = (uint32_t)(row << 7) + (uint32_t)(c8 << 4);
            uint32_t sw = off ^ ((off >> 3) & 0x70);
            size_t ga = (size_t)(bm + row) * K + k0 + (c8 << 3);
            size_t gb = (size_t)(bn + row) * K + k0 + (c8 << 3);
            cp16(buf + sw,         Ah + ga);
            cp16(buf + 16384 + sw, Al + ga);
            cp16(buf + 32768 + sw, Bh + gb);
            cp16(buf + 49152 + sw, Bl + gb);
        }
    };

    const uint32_t xorv   = (uint32_t)(lane & 7) << 4;
    const uint32_t aRowOff = (uint32_t)((wm + (lane & 15)) << 7);
    const uint32_t kaoff  = (uint32_t)((lane >> 4) << 4);
    const uint32_t bRowOff =
        (uint32_t)((wn + (lane & 7) + (((lane >> 4) & 1) << 3)) << 7);
    const uint32_t kboff  = (uint32_t)(((lane >> 3) & 1) << 4);

    float acc[4][4][4] = {};

    const int KCHUNKS = K >> 6;
    issue_stage(0); CP_COMMIT();
    issue_stage(1); CP_COMMIT();

    for (int ch = 0; ch < KCHUNKS; ch++) {
        CP_WAIT(1);
        __syncthreads();
        if (ch + 2 < KCHUNKS) issue_stage(ch + 2);
        CP_COMMIT();

        const uint32_t buf = sb + (uint32_t)(ch % NSTAGE) * STAGE_BYTES;
        const uint32_t aHi = buf + aRowOff;
        const uint32_t aLo = aHi + 16384;
        const uint32_t bHi = buf + 32768 + bRowOff;
        const uint32_t bLo = bHi + 16384;

        #pragma unroll
        for (int s = 0; s < 4; s++) {
            const uint32_t ca = ((uint32_t)(s << 5) + kaoff) ^ xorv;
            const uint32_t cb = ((uint32_t)(s << 5) + kboff) ^ xorv;
            uint32_t ah4[4][4], al4[4][4], bh4[2][4], bl4[2][4];
            #pragma unroll
            for (int mt = 0; mt < 4; mt++) {
                ldmx4(ah4[mt], aHi + (mt << 11) + ca);
                ldmx4(al4[mt], aLo + (mt << 11) + ca);
            }
            #pragma unroll
            for (int nt2 = 0; nt2 < 2; nt2++) {
                ldmx4(bh4[nt2], bHi + (nt2 << 11) + cb);
                ldmx4(bl4[nt2], bLo + (nt2 << 11) + cb);
            }
            #pragma unroll
            for (int mt = 0; mt < 4; mt++)
                #pragma unroll
                for (int nt = 0; nt < 4; nt++) {
                    const uint32_t b0h = bh4[nt >> 1][(nt & 1) * 2];
                    const uint32_t b1h = bh4[nt >> 1][(nt & 1) * 2 + 1];
                    const uint32_t b0l = bl4[nt >> 1][(nt & 1) * 2];
                    const uint32_t b1l = bl4[nt >> 1][(nt & 1) * 2 + 1];
                    mma_bf16(acc[mt][nt], ah4[mt], b0h, b1h);
                    mma_bf16(acc[mt][nt], ah4[mt], b0l, b1l);
                    mma_bf16(acc[mt][nt], al4[mt], b0h, b1h);
                }
        }
    }
    CP_WAIT(0);

    #pragma unroll
    for (int mt = 0; mt < 4; mt++) {
        const int r0 = bm + wm + mt * 16 + (lane >> 2);
        #pragma unroll
        for (int nt = 0; nt < 4; nt++) {
            const int c = bn + wn + nt * 8 + (lane & 3) * 2;
            float2 v0 = make_float2(acc[mt][nt][0], acc[mt][nt][1]);
            float2 v1 = make_float2(acc[mt][nt][2], acc[mt][nt][3]);
            *(float2*)&C[(size_t)r0 * N + c]       = v0;
            *(float2*)&C[(size_t)(r0 + 8) * N + c] = v1;
        }
    }
}

// ---------------------------------------------------------------------------
// Tensor-core flash attention (split-bf16, log2-domain softmax).
// CTA = (b,h) x 128 q-rows; 8 warps x 16 rows. KV tiles of 64, double-buffered.
// smem: Qh 16K | Ql 16K | 2 stages x {Kh 8K, Kl 8K, Vth 8K, Vtl 8K}
// Output: bf16 hi/lo [b,s,1024] (h*64 columns), feeding the out-proj GEMM.
// ---------------------------------------------------------------------------
#define ATT_SMEM (32768 + 2 * 32768)

__global__ void __launch_bounds__(256, 1) attn_mma(
    const __nv_bfloat16* __restrict__ Qh, const __nv_bfloat16* __restrict__ Ql,
    const __nv_bfloat16* __restrict__ Kh, const __nv_bfloat16* __restrict__ Kl,
    const __nv_bfloat16* __restrict__ Vth, const __nv_bfloat16* __restrict__ Vtl,
    __nv_bfloat16* __restrict__ Oh, __nv_bfloat16* __restrict__ Ol) {
    extern __shared__ char smem[];
    const uint32_t sb = smem_to_u32(smem);
    const int tid = threadIdx.x;
    const int lane = tid & 31;
    const int wid = tid >> 5;
    const int bh = blockIdx.y;
    const int q0 = blockIdx.x * 128;

    const size_t qbase = ((size_t)bh * SQ + q0) * HDIM;
    const size_t kbase = (size_t)bh * SQ * HDIM;
    const size_t vbase = (size_t)bh * HDIM * SQ;

    const uint32_t sQh = sb;
    const uint32_t sQl = sb + 16384;

    // --- async loaders ---
    auto issue_q = [&]() {
        #pragma unroll
        for (int i = 0; i < 4; i++) {
            int lin = tid + (i << 8);
            int row = lin >> 3;
            int c8 = lin & 7;
            uint32_t off = (uint32_t)(row << 7) + (uint32_t)(c8 << 4);
            uint32_t sw = off ^ ((off >> 3) & 0x70);
            size_t g = qbase + (size_t)row * HDIM + (c8 << 3);
            cp16(sQh + sw, Qh + g);
            cp16(sQl + sw, Ql + g);
        }
    };
    auto issue_kv = [&](int t) {
        const int kv0 = t << 6;
        const uint32_t stg = sb + 32768 + (uint32_t)(t & 1) * 32768;
        #pragma unroll
        for (int i = 0; i < 2; i++) {
            int lin = tid + (i << 8);
            int row = lin >> 3;
            int c8 = lin & 7;
            uint32_t off = (uint32_t)(row << 7) + (uint32_t)(c8 << 4);
            uint32_t sw = off ^ ((off >> 3) & 0x70);
            size_t gk = kbase + (size_t)(kv0 + row) * HDIM + (c8 << 3);
            size_t gv = vbase + (size_t)row * SQ + kv0 + (c8 << 3);
            cp16(stg + sw,         Kh + gk);
            cp16(stg + 8192 + sw,  Kl + gk);
            cp16(stg + 16384 + sw, Vth + gv);
            cp16(stg + 24576 + sw, Vtl + gv);
        }
    };

    // fragment addressing (identical to gemm_mma, verified)
    const uint32_t xorv = (uint32_t)(lane & 7) << 4;
    const uint32_t qRowOff = (uint32_t)(((wid << 4) + (lane & 15)) << 7);
    const uint32_t kaoff = (uint32_t)((lane >> 4) << 4);
    const uint32_t bRowOff =
        (uint32_t)(((lane & 7) + (((lane >> 4) & 1) << 3)) << 7);
    const uint32_t kboff = (uint32_t)(((lane >> 3) & 1) << 4);

    issue_q(); issue_kv(0); CP_COMMIT();
    issue_kv(1); CP_COMMIT();
    CP_WAIT(1);
    __syncthreads();

    // Q fragments once (warp's 16 rows x full K=64)
    uint32_t qh[4][4], ql[4][4];
    #pragma unroll
    for (int kk = 0; kk < 4; kk++) {
        const uint32_t ca = ((uint32_t)(kk << 5) + kaoff) ^ xorv;
        ldmx4(qh[kk], sQh + qRowOff + ca);
        ldmx4(ql[kk], sQl + qRowOff + ca);
    }

    float m0 = -1e30f, m1 = -1e30f, l0 = 0.0f, l1 = 0.0f;
    float acc_o[8][4] = {};

    for (int t = 0; t < SQ / 64; t++) {
        const uint32_t stg = sb + 32768 + (uint32_t)(t & 1) * 32768;

        // ---- S = Q K^T (3 split passes) ----
        float acc_s[8][4] = {};
        #pragma unroll
        for (int kk = 0; kk < 4; kk++) {
            const uint32_t cb = ((uint32_t)(kk << 5) + kboff) ^ xorv;
            uint32_t kh4[4][4], kl4[4][4];
            #pragma unroll
            for (int nt2 = 0; nt2 < 4; nt2++) {
                ldmx4(kh4[nt2], stg + bRowOff + (nt2 << 11) + cb);
                ldmx4(kl4[nt2], stg + 8192 + bRowOff + (nt2 << 11) + cb);
            }
            #pragma unroll
            for (int nt = 0; nt < 8; nt++) {
                const uint32_t b0h = kh4[nt >> 1][(nt & 1) * 2];
                const uint32_t b1h = kh4[nt >> 1][(nt & 1) * 2 + 1];
                const uint32_t b0l = kl4[nt >> 1][(nt & 1) * 2];
                const uint32_t b1l = kl4[nt >> 1][(nt & 1) * 2 + 1];
                mma_bf16(acc_s[nt], qh[kk], b0h, b1h);
                mma_bf16(acc_s[nt], qh[kk], b0l, b1l);
                mma_bf16(acc_s[nt], ql[kk], b0h, b1h);
            }
        }

        // ---- online softmax (log2 domain; rows r=lane>>2 and r+8) ----
        float mx0 = -1e30f, mx1 = -1e30f;
        #pragma unroll
        for (int nt = 0; nt < 8; nt++) {
            mx0 = fmaxf(mx0, fmaxf(acc_s[nt][0], acc_s[nt][1]));
            mx1 = fmaxf(mx1, fmaxf(acc_s[nt][2], acc_s[nt][3]));
        }
        mx0 = fmaxf(mx0, __shfl_xor_sync(0xffffffffu, mx0, 1));
        mx0 = fmaxf(mx0, __shfl_xor_sync(0xffffffffu, mx0, 2));
        mx1 = fmaxf(mx1, __shfl_xor_sync(0xffffffffu, mx1, 1));
        mx1 = fmaxf(mx1, __shfl_xor_sync(0xffffffffu, mx1, 2));
        const float mn0 = fmaxf(m0, mx0);
        const float mn1 = fmaxf(m1, mx1);
        const float a0 = ex2f(m0 - mn0);
        const float a1 = ex2f(m1 - mn1);
        m0 = mn0; m1 = mn1;
        float rs0 = 0.0f, rs1 = 0.0f;
        #pragma unroll
        for (int nt = 0; nt < 8; nt++) {
            acc_s[nt][0] = ex2f(acc_s[nt][0] - mn0);
            acc_s[nt][1] = ex2f(acc_s[nt][1] - mn0);
            acc_s[nt][2] = ex2f(acc_s[nt][2] - mn1);
            acc_s[nt][3] = ex2f(acc_s[nt][3] - mn1);
            rs0 += acc_s[nt][0] + acc_s[nt][1];
            rs1 += acc_s[nt][2] + acc_s[nt][3];
        }
        l0 = l0 * a0 + rs0;
        l1 = l1 * a1 + rs1;
        #pragma unroll
        for (int nt = 0; nt < 8; nt++) {
            acc_o[nt][0] *= a0; acc_o[nt][1] *= a0;
            acc_o[nt][2] *= a1; acc_o[nt][3] *= a1;
        }

        // ---- pack P into A-fragments hi/lo (truncation split, p >= 0) ----
        uint32_t phi[4][4], plo[4][4];
        #pragma unroll
        for (int kk = 0; kk < 4; kk++) {
            #pragma unroll
            for (int half = 0; half < 2; half++) {
                const float* e = acc_s[2 * kk + half];
                uint32_t b0 = __float_as_uint(e[0]);
                uint32_t b1 = __float_as_uint(e[1]);
                uint32_t b2 = __float_as_uint(e[2]);
                uint32_t b3 = __float_as_uint(e[3]);
                phi[kk][2 * half]     = prmt_hi2(b0, b1);
                phi[kk][2 * half + 1] = prmt_hi2(b2, b3);
                plo[kk][2 * half] = packbf2(
                    e[1] - __uint_as_float(b1 & 0xFFFF0000u),
                    e[0] - __uint_as_float(b0 & 0xFFFF0000u));
                plo[kk][2 * half + 1] = packbf2(
                    e[3] - __uint_as_float(b3 & 0xFFFF0000u),
                    e[2] - __uint_as_float(b2 & 0xFFFF0000u));
            }
        }

        // ---- O += P V (3 split passes); B from Vt tile, same path as K ----
        #pragma unroll
        for (int kk = 0; kk < 4; kk++) {
            const uint32_t cb = ((uint32_t)(kk << 5) + kboff) ^ xorv;
            uint32_t vh4[4][4], vl4[4][4];
            #pragma unroll
            for (int nt2 = 0; nt2 < 4; nt2++) {
                ldmx4(vh4[nt2], stg + 16384 + bRowOff + (nt2 << 11) + cb);
                ldmx4(vl4[nt2], stg + 24576 + bRowOff + (nt2 << 11) + cb);
            }
            #pragma unroll
            for (int nt = 0; nt < 8; nt++) {
                const uint32_t b0h = vh4[nt >> 1][(nt & 1) * 2];
                const uint32_t b1h = vh4[nt >> 1][(nt & 1) * 2 + 1];
                const uint32_t b0l = vl4[nt >> 1][(nt & 1) * 2];
                const uint32_t b1l = vl4[nt >> 1][(nt & 1) * 2 + 1];
                mma_bf16(acc_o[nt], phi[kk], b0h, b1h);
                mma_bf16(acc_o[nt], phi[kk], b0l, b1l);
                mma_bf16(acc_o[nt], plo[kk], b0h, b1h);
            }
        }

        __syncthreads();
        if (t + 2 < SQ / 64) issue_kv(t + 2);
        CP_COMMIT();
        CP_WAIT(1);
        __syncthreads();
    }

    // ---- epilogue: normalize, split hi/lo, store [b,s,1024] ----
    l0 += __shfl_xor_sync(0xffffffffu, l0, 1);
    l0 += __shfl_xor_sync(0xffffffffu, l0, 2);
    l1 += __shfl_xor_sync(0xffffffffu, l1, 1);
    l1 += __shfl_xor_sync(0xffffffffu, l1, 2);
    const float inv0 = 1.0f / l0;
    const float inv1 = 1.0f / l1;
    const int b = bh >> 4, h = bh & 15;
    const int srow = q0 + wid * 16 + (lane >> 2);
    const size_t ob0 = ((size_t)(b * SQ + srow)) * DH + h * HDIM + 2 * (lane & 3);
    const size_t ob1 = ob0 + 8 * DH;
    #pragma unroll
    for (int nt = 0; nt < 8; nt++) {
        float o0 = acc_o[nt][0] * inv0;
        float o1 = acc_o[nt][1] * inv0;
        float o2 = acc_o[nt][2] * inv1;
        float o3 = acc_o[nt][3] * inv1;
        uint32_t u0 = __float_as_uint(o0), u1 = __float_as_uint(o1);
        uint32_t u2 = __float_as_uint(o2), u3 = __float_as_uint(o3);
        *(uint32_t*)(Oh + ob0 + nt * 8) = prmt_hi2(u0, u1);
        *(uint32_t*)(Ol + ob0 + nt * 8) = packbf2(
            o1 - __uint_as_float(u1 & 0xFFFF0000u),
            o0 - __uint_as_float(u0 & 0xFFFF0000u));
        *(uint32_t*)(Oh + ob1 + nt * 8) = prmt_hi2(u2, u3);
        *(uint32_t*)(Ol + ob1 + nt * 8) = packbf2(
            o3 - __uint_as_float(u3 & 0xFFFF0000u),
            o2 - __uint_as_float(u2 & 0xFFFF0000u));
    }
}

// ---------------------------------------------------------------------------
extern "C" void kernel_launch(void* const* d_in, const int* in_sizes, int n_in,
                              void* d_out, int out_size) {
    const float* x     = (const float*)d_in[0];
    const float* w_qkv = (const float*)d_in[1];
    const float* w_out = (const float*)d_in[2];
    float* out = (float*)d_out;

    float* qkv;
    __nv_bfloat16 *xh, *xl, *wqh, *wql, *woh, *wol, *ah, *al;
    __nv_bfloat16 *Qh, *Ql, *Kh, *Kl, *Vth, *Vtl;
    cudaGetSymbolAddress((void**)&qkv, g_qkv);
    cudaGetSymbolAddress((void**)&xh, g_xh);
    cudaGetSymbolAddress((void**)&xl, g_xl);
    cudaGetSymbolAddress((void**)&wqh, g_wqh);
    cudaGetSymbolAddress((void**)&wql, g_wql);
    cudaGetSymbolAddress((void**)&woh, g_woh);
    cudaGetSymbolAddress((void**)&wol, g_wol);
    cudaGetSymbolAddress((void**)&ah, g_ah);
    cudaGetSymbolAddress((void**)&al, g_al);
    cudaGetSymbolAddress((void**)&Qh, g_Qh);
    cudaGetSymbolAddress((void**)&Ql, g_Ql);
    cudaGetSymbolAddress((void**)&Kh, g_Kh);
    cudaGetSymbolAddress((void**)&Kl, g_Kl);
    cudaGetSymbolAddress((void**)&Vth, g_Vth);
    cudaGetSymbolAddress((void**)&Vtl, g_Vtl);

    cudaFuncSetAttribute(gemm_mma, cudaFuncAttributeMaxDynamicSharedMemorySize,
                         GSM_TOTAL);
    cudaFuncSetAttribute(attn_mma, cudaFuncAttributeMaxDynamicSharedMemorySize,
                         ATT_SMEM);

    const int M = BZ * SQ;                 // 4096
    const int nX  = M * DH / 4;
    const int nWq = 3 * DH * DH / 4;
    const int nWo = DH * DH / 4;

    split_hl<<<(nX + 255) / 256, 256>>>((const float4*)x, (uint2*)xh, (uint2*)xl, nX);
    split_hl<<<(nWq + 255) / 256, 256>>>((const float4*)w_qkv, (uint2*)wqh, (uint2*)wql, nWq);
    split_hl<<<(nWo + 255) / 256, 256>>>((const float4*)w_out, (uint2*)woh, (uint2*)wol, nWo);

    // 1) QKV projection -> qkv fp32
    gemm_mma<<<dim3(3 * DH / 128, M / 128), 256, GSM_TOTAL>>>(xh, xl, wqh, wql,
                                                              qkv, M, 3 * DH, DH);

    // 2) prep: head-major bf16 hi/lo Q,K,V^T
    prep_qkv<<<dim3(SQ / 64, BZ * NH), 256>>>(qkv,
        (uint2*)Qh, (uint2*)Ql, (uint2*)Kh, (uint2*)Kl, (uint2*)Vth, (uint2*)Vtl);

    // 3) attention -> bf16 hi/lo [b,s,1024]
    attn_mma<<<dim3(SQ / 128, BZ * NH), 256, ATT_SMEM>>>(Qh, Ql, Kh, Kl, Vth, Vtl,
                                                         ah, al);

    // 4) output projection -> d_out (fp32)
    gemm_mma<<<dim3(DH / 128, M / 128), 256, GSM_TOTAL>>>(ah, al, woh, wol, out,
                                                          M, DH, DH);
}